// round 3
// baseline (speedup 1.0000x reference)
#include <cuda_runtime.h>
#include <cuda_bf16.h>
#include <math.h>
#include <cstdint>

#define BATCH 32
#define CH    64
#define FM    128
#define HW    (FM*FM)          // 16384
#define CHW   (CH*HW)          // 1048576
#define TOTAL (BATCH*CHW)      // 33554432

// Scratch (__device__ globals: allocation-free rule)
__device__ unsigned short g_qh[TOTAL];   // bf16 hi of q
__device__ unsigned short g_ql[TOTAL];   // bf16 lo of q
__device__ unsigned short g_kh[TOTAL];   // bf16 hi of keff = k + pos_code
__device__ unsigned short g_kl[TOTAL];   // bf16 lo
__device__ float          g_v [TOTAL];   // fp32 v

// ---------------------------------------------------------------------------
// Kernel 1: QKV projection (FFMA, at fp32 floor). Emits bf16 hi/lo splits for
// q and keff = k + pos_code; v stays fp32.
// ---------------------------------------------------------------------------
__global__ __launch_bounds__(256) void qkv_kernel(
    const float* __restrict__ x,
    const float* __restrict__ wq, const float* __restrict__ bq,
    const float* __restrict__ wk, const float* __restrict__ bk,
    const float* __restrict__ wv, const float* __restrict__ bv,
    const float* __restrict__ pos)
{
    extern __shared__ float xs[];      // [64][256]
    __shared__ float wsT[64 * 68];
    __shared__ float bsm[64];
    __shared__ float pcs[256];

    const int tid  = threadIdx.x;
    const int b    = blockIdx.y;
    const int pix0 = blockIdx.x * 256;
    const int to   = tid >> 6;
    const int tp   = tid & 63;

    {
        const float* xp = x + (size_t)b * CHW + pix0 + tid;
        #pragma unroll
        for (int c = 0; c < 64; ++c)
            xs[c * 256 + tid] = xp[(size_t)c * HW];
    }
    pcs[tid] = pos[pix0 + tid];

    const float* W[3]  = {wq, wk, wv};
    const float* Bv[3] = {bq, bk, bv};

    for (int m = 0; m < 3; ++m) {
        __syncthreads();
        #pragma unroll
        for (int i = 0; i < 16; ++i) {
            int idx = i * 256 + tid;
            int o = idx >> 6, c = idx & 63;
            wsT[c * 68 + o] = W[m][idx];
        }
        if (tid < 64) bsm[tid] = Bv[m][tid];
        __syncthreads();

        float acc[16][4];
        #pragma unroll
        for (int i = 0; i < 16; ++i)
            #pragma unroll
            for (int j = 0; j < 4; ++j) acc[i][j] = 0.f;

        #pragma unroll 4
        for (int c = 0; c < 64; ++c) {
            float xv[4];
            *(float4*)&xv[0] = *(const float4*)&xs[c * 256 + tp * 4];
            float w[16];
            const float4* wr = (const float4*)&wsT[c * 68 + to * 16];
            *(float4*)&w[0]  = wr[0];
            *(float4*)&w[4]  = wr[1];
            *(float4*)&w[8]  = wr[2];
            *(float4*)&w[12] = wr[3];
            #pragma unroll
            for (int i = 0; i < 16; ++i)
                #pragma unroll
                for (int j = 0; j < 4; ++j)
                    acc[i][j] += w[i] * xv[j];
        }

        const size_t bbase = (size_t)b * CHW;
        #pragma unroll
        for (int i = 0; i < 16; ++i) {
            int o = to * 16 + i;
            float bb = bsm[o];
            float r[4];
            #pragma unroll
            for (int j = 0; j < 4; ++j) r[j] = acc[i][j] + bb;
            size_t off = bbase + (size_t)o * HW + pix0 + tp * 4;

            if (m == 2) {
                *(float4*)&g_v[off] = *(float4*)&r[0];
            } else {
                if (m == 1) {
                    #pragma unroll
                    for (int j = 0; j < 4; ++j) r[j] += pcs[tp * 4 + j];
                }
                unsigned short hi[4], lo[4];
                #pragma unroll
                for (int j = 0; j < 4; ++j) {
                    __nv_bfloat16 h = __float2bfloat16(r[j]);
                    hi[j] = __bfloat16_as_ushort(h);
                    lo[j] = __bfloat16_as_ushort(__float2bfloat16(r[j] - __bfloat162float(h)));
                }
                uint2 hp = make_uint2((uint32_t)hi[0] | ((uint32_t)hi[1] << 16),
                                      (uint32_t)hi[2] | ((uint32_t)hi[3] << 16));
                uint2 lp = make_uint2((uint32_t)lo[0] | ((uint32_t)lo[1] << 16),
                                      (uint32_t)lo[2] | ((uint32_t)lo[3] << 16));
                if (m == 0) {
                    *(uint2*)&g_qh[off] = hp;
                    *(uint2*)&g_ql[off] = lp;
                } else {
                    *(uint2*)&g_kh[off] = hp;
                    *(uint2*)&g_kl[off] = lp;
                }
            }
        }
    }
}

// ---------------------------------------------------------------------------
// Kernel 2: per-(b,c) attention on mma.sync (HMMA, base sm_103-legal).
// S = Qh*Kh' + Qh*Kl' + Ql*Kh' (bf16x3 split, fp32 accum in registers),
// global softmax over 16384 logits, out = att * v.
//
// Smem: 4 tiles [128 rows][136 halves] (pad 136 -> bank = (4g+t)%32,
// conflict-free for fragment loads). 8 warps, each owns 32x64 of S.
// mma.sync.m16n8k16.row.col: A reg = Q[r][2t..2t+1] pair, B reg =
// K[n][2t..2t+1] pair -> all operand loads are contiguous 32-bit LDS.
// ---------------------------------------------------------------------------
#define TSTRIDE 136
#define TILE_HALVES (128 * TSTRIDE)            // 17408
#define AT_SMEM (4 * TILE_HALVES * 2)          // 139264 bytes
#define STG_STRIDE 132

__device__ __forceinline__ void mma_bf16(float* d, const uint32_t* a,
                                         uint32_t b0, uint32_t b1) {
    asm volatile(
        "mma.sync.aligned.m16n8k16.row.col.f32.bf16.bf16.f32 "
        "{%0,%1,%2,%3}, {%4,%5,%6,%7}, {%8,%9}, {%0,%1,%2,%3};"
        : "+f"(d[0]), "+f"(d[1]), "+f"(d[2]), "+f"(d[3])
        : "r"(a[0]), "r"(a[1]), "r"(a[2]), "r"(a[3]), "r"(b0), "r"(b1));
}

__global__ __launch_bounds__(256) void attn_mma_kernel(float* __restrict__ out)
{
    extern __shared__ __align__(16) unsigned short sm[];
    __shared__ float redm[8], reds[8];

    const int tid = threadIdx.x;
    const int wid = tid >> 5;
    const int lid = tid & 31;
    const int g   = lid >> 2;        // group id 0..7
    const int t   = lid & 3;         // thread-in-group 0..3
    const size_t base = (size_t)blockIdx.x * HW;

    unsigned short* sQh = sm;
    unsigned short* sQl = sm + TILE_HALVES;
    unsigned short* sKh = sm + 2 * TILE_HALVES;
    unsigned short* sKl = sm + 3 * TILE_HALVES;

    // ---- load 4 bf16 tiles into padded smem (coalesced 16B chunks) ----
    {
        const unsigned short* srcs[4] = {g_qh + base, g_ql + base, g_kh + base, g_kl + base};
        unsigned short* dsts[4] = {sQh, sQl, sKh, sKl};
        #pragma unroll
        for (int tt = 0; tt < 4; ++tt) {
            const uint4* src = (const uint4*)srcs[tt];
            unsigned short* dst = dsts[tt];
            #pragma unroll
            for (int i = 0; i < 8; ++i) {
                int cw = i * 256 + tid;            // 16B chunk id, 2048 per tile
                int row = cw >> 4;
                int c8  = cw & 15;
                *(uint4*)&dst[row * TSTRIDE + c8 * 8] = src[cw];
            }
        }
    }
    __syncthreads();

    // ---- warp tile: rows m0..m0+31, cols n0..n0+63 ----
    const int m0 = (wid & 3) * 32;
    const int n0 = (wid >> 2) * 64;

    float acc[2][8][4];
    #pragma unroll
    for (int mt = 0; mt < 2; ++mt)
        #pragma unroll
        for (int nt = 0; nt < 8; ++nt)
            #pragma unroll
            for (int j = 0; j < 4; ++j) acc[mt][nt][j] = 0.f;

    const unsigned short* Aop[3] = {sQh, sQh, sQl};
    const unsigned short* Bop[3] = {sKh, sKl, sKh};

    for (int p = 0; p < 3; ++p) {
        const unsigned short* A = Aop[p];
        const unsigned short* B = Bop[p];
        #pragma unroll
        for (int kk = 0; kk < 8; ++kk) {
            const int c = kk * 16 + 2 * t;
            uint32_t afr[2][4];
            #pragma unroll
            for (int mt = 0; mt < 2; ++mt) {
                const int r = m0 + mt * 16 + g;
                afr[mt][0] = *(const uint32_t*)&A[r * TSTRIDE + c];
                afr[mt][1] = *(const uint32_t*)&A[(r + 8) * TSTRIDE + c];
                afr[mt][2] = *(const uint32_t*)&A[r * TSTRIDE + c + 8];
                afr[mt][3] = *(const uint32_t*)&A[(r + 8) * TSTRIDE + c + 8];
            }
            #pragma unroll
            for (int nt = 0; nt < 8; ++nt) {
                const int rn = n0 + nt * 8 + g;
                uint32_t b0 = *(const uint32_t*)&B[rn * TSTRIDE + c];
                uint32_t b1 = *(const uint32_t*)&B[rn * TSTRIDE + c + 8];
                mma_bf16(acc[0][nt], afr[0], b0, b1);
                mma_bf16(acc[1][nt], afr[1], b0, b1);
            }
        }
    }

    // ---- global max over all 16384 logits ----
    float mx = acc[0][0][0];
    #pragma unroll
    for (int mt = 0; mt < 2; ++mt)
        #pragma unroll
        for (int nt = 0; nt < 8; ++nt)
            #pragma unroll
            for (int j = 0; j < 4; ++j) mx = fmaxf(mx, acc[mt][nt][j]);
    #pragma unroll
    for (int o = 16; o; o >>= 1) mx = fmaxf(mx, __shfl_xor_sync(0xffffffffu, mx, o));
    if (lid == 0) redm[wid] = mx;
    __syncthreads();
    float gm = redm[0];
    #pragma unroll
    for (int w = 1; w < 8; ++w) gm = fmaxf(gm, redm[w]);

    // ---- exp + global sum ----
    float s = 0.f;
    #pragma unroll
    for (int mt = 0; mt < 2; ++mt)
        #pragma unroll
        for (int nt = 0; nt < 8; ++nt)
            #pragma unroll
            for (int j = 0; j < 4; ++j) {
                float e = __expf(acc[mt][nt][j] - gm);
                acc[mt][nt][j] = e;
                s += e;
            }
    #pragma unroll
    for (int o = 16; o; o >>= 1) s += __shfl_xor_sync(0xffffffffu, s, o);
    if (lid == 0) reds[wid] = s;
    __syncthreads();
    float gs = 0.f;
    #pragma unroll
    for (int w = 0; w < 8; ++w) gs += reds[w];
    const float inv = 1.0f / gs;

    // ---- stage normalized att into smem (reuse tile region) ----
    __syncthreads();   // everyone done reading tiles before overwrite
    float* stg = (float*)sm;
    #pragma unroll
    for (int mt = 0; mt < 2; ++mt) {
        const int r = m0 + mt * 16 + g;
        #pragma unroll
        for (int nt = 0; nt < 8; ++nt) {
            const int cN = n0 + nt * 8 + 2 * t;
            stg[r * STG_STRIDE + cN]           = acc[mt][nt][0] * inv;
            stg[r * STG_STRIDE + cN + 1]       = acc[mt][nt][1] * inv;
            stg[(r + 8) * STG_STRIDE + cN]     = acc[mt][nt][2] * inv;
            stg[(r + 8) * STG_STRIDE + cN + 1] = acc[mt][nt][3] * inv;
        }
    }
    __syncthreads();

    // ---- coalesced out = att * v ----
    const float* vg = g_v + base;
    float* og = out + base;
    #pragma unroll
    for (int i = 0; i < 64; ++i) {
        int idx = i * 256 + tid;
        int r = idx >> 7, c = idx & 127;
        og[idx] = stg[r * STG_STRIDE + c] * vg[idx];
    }
}

// ---------------------------------------------------------------------------
extern "C" void kernel_launch(void* const* d_in, const int* in_sizes, int n_in,
                              void* d_out, int out_size)
{
    (void)in_sizes; (void)n_in; (void)out_size;
    const float* x  = (const float*)d_in[0];
    const float* wq = (const float*)d_in[1];
    const float* bq = (const float*)d_in[2];
    const float* wk = (const float*)d_in[3];
    const float* bk = (const float*)d_in[4];
    const float* wv = (const float*)d_in[5];
    const float* bv = (const float*)d_in[6];
    const float* pc = (const float*)d_in[7];
    float* out = (float*)d_out;

    cudaFuncSetAttribute(qkv_kernel, cudaFuncAttributeMaxDynamicSharedMemorySize, 65536);
    cudaFuncSetAttribute(attn_mma_kernel, cudaFuncAttributeMaxDynamicSharedMemorySize, AT_SMEM);

    qkv_kernel<<<dim3(HW / 256, BATCH), 256, 65536>>>(x, wq, bq, wk, bk, wv, bv, pc);
    attn_mma_kernel<<<BATCH * CH, 256, AT_SMEM>>>(out);
}

// round 4
// speedup vs baseline: 1.4019x; 1.4019x over previous
#include <cuda_runtime.h>
#include <cuda_bf16.h>
#include <cstdint>

#define BATCH 32
#define CH    64
#define FM    128
#define HW    (FM*FM)          // 16384
#define CHW   (CH*HW)          // 1048576
#define TOTAL (BATCH*CHW)      // 33554432

// Scratch (__device__ globals: allocation-free rule)
__device__ unsigned short g_qh[TOTAL];   // bf16 hi of q
__device__ unsigned short g_ql[TOTAL];   // bf16 lo of q
__device__ unsigned short g_kh[TOTAL];   // bf16 hi of keff = k + pos_code
__device__ unsigned short g_kl[TOTAL];   // bf16 lo
__device__ float          g_v [TOTAL];   // fp32 v

// ---------------------------------------------------------------------------
// helpers
// ---------------------------------------------------------------------------
__device__ __forceinline__ uint32_t sptr(const void* p) {
    return (uint32_t)__cvta_generic_to_shared(p);
}
__device__ __forceinline__ void ldm_x4(uint32_t* r, uint32_t a) {
    asm volatile("ldmatrix.sync.aligned.m8n8.x4.shared.b16 {%0,%1,%2,%3}, [%4];"
                 : "=r"(r[0]), "=r"(r[1]), "=r"(r[2]), "=r"(r[3]) : "r"(a));
}
__device__ __forceinline__ void mma_bf16(float* d, const uint32_t* a,
                                         uint32_t b0, uint32_t b1) {
    asm volatile(
        "mma.sync.aligned.m16n8k16.row.col.f32.bf16.bf16.f32 "
        "{%0,%1,%2,%3}, {%4,%5,%6,%7}, {%8,%9}, {%0,%1,%2,%3};"
        : "+f"(d[0]), "+f"(d[1]), "+f"(d[2]), "+f"(d[3])
        : "r"(a[0]), "r"(a[1]), "r"(a[2]), "r"(a[3]), "r"(b0), "r"(b1));
}
__device__ __forceinline__ void split_bf16(float v, unsigned short& h, unsigned short& l) {
    __nv_bfloat16 hb = __float2bfloat16(v);
    h = __bfloat16_as_ushort(hb);
    l = __bfloat16_as_ushort(__float2bfloat16(v - __bfloat162float(hb)));
}

// ---------------------------------------------------------------------------
// Kernel 1: QKV projection on mma.sync, bf16x3 split (Wh*Xh + Wh*Xl + Wl*Xh).
// Block: batch b, all 64 out-ch, 256-pixel tile. 512 threads = 16 warps,
// warp tile m16 (out-ch) x n64 (pixels). A = W [o][c] k-contig; B = x^T
// [pixel][c] k-contig, built by conflict-free STS.128 transpose-split.
// Stride 72 halves: ldmatrix 16B-chunk index 9i mod 8 = i -> conflict-free.
// ---------------------------------------------------------------------------
#define XSTR 72
#define QKV_SMEM ((512*XSTR + 6*64*XSTR) * 2)   // 129024 bytes

__global__ __launch_bounds__(512) void qkv_mma_kernel(
    const float* __restrict__ x,
    const float* __restrict__ wq, const float* __restrict__ bq,
    const float* __restrict__ wk, const float* __restrict__ bk,
    const float* __restrict__ wv, const float* __restrict__ bv,
    const float* __restrict__ pos)
{
    extern __shared__ __align__(16) unsigned short qs[];
    unsigned short* sxh = qs;                    // [256][72]
    unsigned short* sxl = qs + 256 * XSTR;
    unsigned short* sw  = qs + 512 * XSTR;       // [m*2+hl][64][72]
    __shared__ float bsm[192];
    __shared__ float pcs[256];

    const int tid  = threadIdx.x;
    const int b    = blockIdx.y;
    const int pix0 = blockIdx.x * 256;

    if (tid < 256) pcs[tid] = pos[pix0 + tid];
    if (tid < 192) {
        const float* bp = (tid < 64) ? bq : (tid < 128) ? bk : bv;
        bsm[tid] = bp[tid & 63];
    }

    // weights: 3 x 4096 elements, split to hi/lo
    #pragma unroll
    for (int i = 0; i < 24; ++i) {
        int idx = i * 512 + tid;
        int m = idx >> 12, r = idx & 4095;
        int o = r >> 6, c = r & 63;
        const float* wp = (m == 0) ? wq : (m == 1) ? wk : wv;
        unsigned short h, l;
        split_bf16(wp[r], h, l);
        sw[(2 * m) * 64 * XSTR + o * XSTR + c]     = h;
        sw[(2 * m + 1) * 64 * XSTR + o * XSTR + c] = l;
    }

    // x transpose + split: thread owns pixel p, 8-channel groups
    {
        const float* xb = x + (size_t)b * CHW + pix0;
        const int p  = tid & 255;
        const int cg = tid >> 8;
        #pragma unroll
        for (int i = 0; i < 4; ++i) {
            int c0 = (cg + 2 * i) * 8;
            unsigned short h[8], l[8];
            #pragma unroll
            for (int j = 0; j < 8; ++j)
                split_bf16(xb[(size_t)(c0 + j) * HW + p], h[j], l[j]);
            uint4 hv, lv;
            hv.x = (uint32_t)h[0] | ((uint32_t)h[1] << 16);
            hv.y = (uint32_t)h[2] | ((uint32_t)h[3] << 16);
            hv.z = (uint32_t)h[4] | ((uint32_t)h[5] << 16);
            hv.w = (uint32_t)h[6] | ((uint32_t)h[7] << 16);
            lv.x = (uint32_t)l[0] | ((uint32_t)l[1] << 16);
            lv.y = (uint32_t)l[2] | ((uint32_t)l[3] << 16);
            lv.z = (uint32_t)l[4] | ((uint32_t)l[5] << 16);
            lv.w = (uint32_t)l[6] | ((uint32_t)l[7] << 16);
            *(uint4*)&sxh[p * XSTR + c0] = hv;
            *(uint4*)&sxl[p * XSTR + c0] = lv;
        }
    }
    __syncthreads();

    const int wid = tid >> 5, lid = tid & 31, g = lid >> 2, t = lid & 3;
    const int m0 = (wid & 3) * 16;      // out-channel tile
    const int n0 = (wid >> 2) * 64;     // pixel tile

    const uint32_t sx_h = sptr(sxh), sx_l = sptr(sxl);
    const uint32_t aoff  = (uint32_t)((m0 + (lid & 15)) * XSTR + ((lid & 16) ? 8 : 0)) * 2;
    const uint32_t boff0 = (uint32_t)((n0 + lid) * XSTR) * 2;
    const uint32_t boff1 = (uint32_t)((n0 + 32 + lid) * XSTR) * 2;
    const size_t   ob    = (size_t)b * CHW;

    #pragma unroll
    for (int m = 0; m < 3; ++m) {
        const uint32_t wbh = sptr(sw + (2 * m) * 64 * XSTR);
        const uint32_t wbl = wbh + 64 * XSTR * 2;

        uint32_t ah[4][4], al[4][4];
        #pragma unroll
        for (int kk = 0; kk < 4; ++kk) {
            ldm_x4(ah[kk], wbh + aoff + kk * 32);
            ldm_x4(al[kk], wbl + aoff + kk * 32);
        }

        float acc[8][4];
        #pragma unroll
        for (int nt = 0; nt < 8; ++nt)
            #pragma unroll
            for (int j = 0; j < 4; ++j) acc[nt][j] = 0.f;

        #pragma unroll
        for (int kk = 0; kk < 4; ++kk) {
            const uint32_t ko = kk * 32;
            uint32_t bh[16], bl[16];
            ldm_x4(bh + 0,  sx_h + boff0 + ko);
            ldm_x4(bh + 4,  sx_h + boff0 + ko + 16);
            ldm_x4(bh + 8,  sx_h + boff1 + ko);
            ldm_x4(bh + 12, sx_h + boff1 + ko + 16);
            ldm_x4(bl + 0,  sx_l + boff0 + ko);
            ldm_x4(bl + 4,  sx_l + boff0 + ko + 16);
            ldm_x4(bl + 8,  sx_l + boff1 + ko);
            ldm_x4(bl + 12, sx_l + boff1 + ko + 16);
            #pragma unroll
            for (int hf = 0; hf < 2; ++hf)
                #pragma unroll
                for (int nt = 0; nt < 4; ++nt) {
                    float* ac = acc[hf * 4 + nt];
                    uint32_t b0 = bh[hf * 8 + nt], b1 = bh[hf * 8 + 4 + nt];
                    mma_bf16(ac, ah[kk], b0, b1);
                    mma_bf16(ac, ah[kk], bl[hf * 8 + nt], bl[hf * 8 + 4 + nt]);
                    mma_bf16(ac, al[kk], b0, b1);
                }
        }

        // epilogue
        const int r0 = m0 + g, r1 = r0 + 8;
        const float b0f = bsm[m * 64 + r0], b1f = bsm[m * 64 + r1];
        #pragma unroll
        for (int nt = 0; nt < 8; ++nt) {
            int px = n0 + nt * 8 + 2 * t;
            float c0 = acc[nt][0] + b0f;
            float c1 = acc[nt][1] + b0f;
            float c2 = acc[nt][2] + b1f;
            float c3 = acc[nt][3] + b1f;
            if (m == 1) {
                float p0 = pcs[px], p1 = pcs[px + 1];
                c0 += p0; c1 += p1; c2 += p0; c3 += p1;
            }
            size_t o0 = ob + (size_t)r0 * HW + pix0 + px;
            size_t o1 = ob + (size_t)r1 * HW + pix0 + px;
            if (m == 2) {
                *(float2*)&g_v[o0] = make_float2(c0, c1);
                *(float2*)&g_v[o1] = make_float2(c2, c3);
            } else {
                unsigned short h0, l0, h1, l1, h2, l2, h3, l3;
                split_bf16(c0, h0, l0);
                split_bf16(c1, h1, l1);
                split_bf16(c2, h2, l2);
                split_bf16(c3, h3, l3);
                uint32_t hp0 = (uint32_t)h0 | ((uint32_t)h1 << 16);
                uint32_t lp0 = (uint32_t)l0 | ((uint32_t)l1 << 16);
                uint32_t hp1 = (uint32_t)h2 | ((uint32_t)h3 << 16);
                uint32_t lp1 = (uint32_t)l2 | ((uint32_t)l3 << 16);
                if (m == 0) {
                    *(uint32_t*)&g_qh[o0] = hp0; *(uint32_t*)&g_ql[o0] = lp0;
                    *(uint32_t*)&g_qh[o1] = hp1; *(uint32_t*)&g_ql[o1] = lp1;
                } else {
                    *(uint32_t*)&g_kh[o0] = hp0; *(uint32_t*)&g_kl[o0] = lp0;
                    *(uint32_t*)&g_kh[o1] = hp1; *(uint32_t*)&g_kl[o1] = lp1;
                }
            }
        }
    }
}

// ---------------------------------------------------------------------------
// Kernel 2: per-(b,c) attention, mma.sync + ldmatrix, bf16x3 split.
// 512 threads = 16 warps, warp tile 32x32 of S. Per k16 step: 8 ldmatrix.x4
// feed 24 mma (Ah/Al/Bh/Bl loaded once, all 3 products reuse them).
// ---------------------------------------------------------------------------
#define TSTR 136
#define THALVES (128 * TSTR)
#define AT_SMEM (4 * THALVES * 2)   // 139264 bytes
#define SSTR 132

__global__ __launch_bounds__(512) void attn_mma_kernel(float* __restrict__ out)
{
    extern __shared__ __align__(16) unsigned short sm[];
    __shared__ float redm[16], reds[16];

    const int tid = threadIdx.x, wid = tid >> 5, lid = tid & 31;
    const int g = lid >> 2, t = lid & 3;
    const size_t base = (size_t)blockIdx.x * HW;

    // load 4 bf16 tiles (qh, ql, kh, kl), coalesced 16B chunks
    {
        const unsigned short* srcs[4] = {g_qh + base, g_ql + base, g_kh + base, g_kl + base};
        #pragma unroll
        for (int tt = 0; tt < 4; ++tt) {
            const uint4* src = (const uint4*)srcs[tt];
            unsigned short* dst = sm + tt * THALVES;
            #pragma unroll
            for (int i = 0; i < 4; ++i) {
                int cw = i * 512 + tid;
                int row = cw >> 4, c8 = cw & 15;
                *(uint4*)&dst[row * TSTR + c8 * 8] = src[cw];
            }
        }
    }
    __syncthreads();

    const int m0 = (wid & 3) * 32, n0 = (wid >> 2) * 32;
    const uint32_t qh_b = sptr(sm);
    const uint32_t ql_b = qh_b + THALVES * 2;
    const uint32_t kh_b = qh_b + 2 * THALVES * 2;
    const uint32_t kl_b = qh_b + 3 * THALVES * 2;
    const uint32_t aoff0 = (uint32_t)((m0 + (lid & 15)) * TSTR + ((lid & 16) ? 8 : 0)) * 2;
    const uint32_t aoff1 = aoff0 + 16 * TSTR * 2;
    const uint32_t boff  = (uint32_t)((n0 + lid) * TSTR) * 2;

    float acc[2][4][4];
    #pragma unroll
    for (int mt = 0; mt < 2; ++mt)
        #pragma unroll
        for (int nt = 0; nt < 4; ++nt)
            #pragma unroll
            for (int j = 0; j < 4; ++j) acc[mt][nt][j] = 0.f;

    #pragma unroll
    for (int kk = 0; kk < 8; ++kk) {
        const uint32_t ko = kk * 32;
        uint32_t ah[2][4], al[2][4], bh[8], bl[8];
        ldm_x4(ah[0], qh_b + aoff0 + ko);
        ldm_x4(ah[1], qh_b + aoff1 + ko);
        ldm_x4(al[0], ql_b + aoff0 + ko);
        ldm_x4(al[1], ql_b + aoff1 + ko);
        ldm_x4(bh,     kh_b + boff + ko);
        ldm_x4(bh + 4, kh_b + boff + ko + 16);
        ldm_x4(bl,     kl_b + boff + ko);
        ldm_x4(bl + 4, kl_b + boff + ko + 16);
        #pragma unroll
        for (int mt = 0; mt < 2; ++mt)
            #pragma unroll
            for (int nt = 0; nt < 4; ++nt) {
                mma_bf16(acc[mt][nt], ah[mt], bh[nt], bh[4 + nt]);
                mma_bf16(acc[mt][nt], ah[mt], bl[nt], bl[4 + nt]);
                mma_bf16(acc[mt][nt], al[mt], bh[nt], bh[4 + nt]);
            }
    }

    float* l = &acc[0][0][0];   // 32 contiguous logits per lane

    // ---- global max ----
    float mx = l[0];
    #pragma unroll
    for (int j = 1; j < 32; ++j) mx = fmaxf(mx, l[j]);
    #pragma unroll
    for (int o = 16; o; o >>= 1) mx = fmaxf(mx, __shfl_xor_sync(0xffffffffu, mx, o));
    if (lid == 0) redm[wid] = mx;
    __syncthreads();
    float gm = redm[0];
    #pragma unroll
    for (int w = 1; w < 16; ++w) gm = fmaxf(gm, redm[w]);

    // ---- exp + global sum ----
    float s = 0.f;
    #pragma unroll
    for (int j = 0; j < 32; ++j) {
        l[j] = __expf(l[j] - gm);
        s += l[j];
    }
    #pragma unroll
    for (int o = 16; o; o >>= 1) s += __shfl_xor_sync(0xffffffffu, s, o);
    if (lid == 0) reds[wid] = s;
    __syncthreads();
    float gs = 0.f;
    #pragma unroll
    for (int w = 0; w < 16; ++w) gs += reds[w];
    const float inv = 1.0f / gs;

    // ---- stage normalized att into smem (tiles no longer needed) ----
    float* stg = (float*)sm;
    #pragma unroll
    for (int mt = 0; mt < 2; ++mt) {
        const int r0 = m0 + mt * 16 + g;
        #pragma unroll
        for (int nt = 0; nt < 4; ++nt) {
            const int cN = n0 + nt * 8 + 2 * t;
            stg[r0 * SSTR + cN]           = acc[mt][nt][0] * inv;
            stg[r0 * SSTR + cN + 1]       = acc[mt][nt][1] * inv;
            stg[(r0 + 8) * SSTR + cN]     = acc[mt][nt][2] * inv;
            stg[(r0 + 8) * SSTR + cN + 1] = acc[mt][nt][3] * inv;
        }
    }
    __syncthreads();

    // ---- coalesced out = att * v ----
    const float* vg = g_v + base;
    float* og = out + base;
    #pragma unroll
    for (int i = 0; i < 32; ++i) {
        int idx = i * 512 + tid;
        int r = idx >> 7, c = idx & 127;
        og[idx] = stg[r * SSTR + c] * vg[idx];
    }
}

// ---------------------------------------------------------------------------
extern "C" void kernel_launch(void* const* d_in, const int* in_sizes, int n_in,
                              void* d_out, int out_size)
{
    (void)in_sizes; (void)n_in; (void)out_size;
    const float* x  = (const float*)d_in[0];
    const float* wq = (const float*)d_in[1];
    const float* bq = (const float*)d_in[2];
    const float* wk = (const float*)d_in[3];
    const float* bk = (const float*)d_in[4];
    const float* wv = (const float*)d_in[5];
    const float* bv = (const float*)d_in[6];
    const float* pc = (const float*)d_in[7];
    float* out = (float*)d_out;

    cudaFuncSetAttribute(qkv_mma_kernel, cudaFuncAttributeMaxDynamicSharedMemorySize, QKV_SMEM);
    cudaFuncSetAttribute(attn_mma_kernel, cudaFuncAttributeMaxDynamicSharedMemorySize, AT_SMEM);

    qkv_mma_kernel<<<dim3(HW / 256, BATCH), 512, QKV_SMEM>>>(x, wq, bq, wk, bk, wv, bv, pc);
    attn_mma_kernel<<<BATCH * CH, 512, AT_SMEM>>>(out);
}

// round 5
// speedup vs baseline: 2.0185x; 1.4398x over previous
#include <cuda_runtime.h>
#include <cuda_bf16.h>
#include <cstdint>

#define BATCH 32
#define CH    64
#define FM    128
#define HW    (FM*FM)          // 16384
#define CHW   (CH*HW)          // 1048576
#define TOTAL (BATCH*CHW)      // 33554432

// Scratch (__device__ globals: allocation-free rule)
__device__ unsigned short g_qh[TOTAL];   // bf16 hi of q
__device__ unsigned short g_ql[TOTAL];   // bf16 lo of q
__device__ unsigned short g_kh[TOTAL];   // bf16 hi of keff = k + pos_code
__device__ unsigned short g_kl[TOTAL];   // bf16 lo
__device__ float          g_v [TOTAL];   // fp32 v

// ---------------------------------------------------------------------------
// helpers
// ---------------------------------------------------------------------------
__device__ __forceinline__ uint32_t sptr(const void* p) {
    return (uint32_t)__cvta_generic_to_shared(p);
}
__device__ __forceinline__ void ldm_x4(uint32_t* r, uint32_t a) {
    asm volatile("ldmatrix.sync.aligned.m8n8.x4.shared.b16 {%0,%1,%2,%3}, [%4];"
                 : "=r"(r[0]), "=r"(r[1]), "=r"(r[2]), "=r"(r[3]) : "r"(a));
}
__device__ __forceinline__ void mma_bf16(float* d, const uint32_t* a,
                                         uint32_t b0, uint32_t b1) {
    asm volatile(
        "mma.sync.aligned.m16n8k16.row.col.f32.bf16.bf16.f32 "
        "{%0,%1,%2,%3}, {%4,%5,%6,%7}, {%8,%9}, {%0,%1,%2,%3};"
        : "+f"(d[0]), "+f"(d[1]), "+f"(d[2]), "+f"(d[3])
        : "r"(a[0]), "r"(a[1]), "r"(a[2]), "r"(a[3]), "r"(b0), "r"(b1));
}
__device__ __forceinline__ void split_bf16(float v, unsigned short& h, unsigned short& l) {
    __nv_bfloat16 hb = __float2bfloat16(v);
    h = __bfloat16_as_ushort(hb);
    l = __bfloat16_as_ushort(__float2bfloat16(v - __bfloat162float(hb)));
}

// ---------------------------------------------------------------------------
// Kernel 1: QKV projection on mma.sync, bf16x3 split (Wh*Xh + Wh*Xl + Wl*Xh).
// 2 blocks/SM: weights staged per-m (18KB reused), x tiles resident (72KB).
// 512 threads = 16 warps, warp tile m16 (out-ch) x n64 (pixels).
// ---------------------------------------------------------------------------
#define XSTR 72
#define QKV_SMEM ((512*XSTR + 2*64*XSTR) * 2)   // 92160 bytes

__global__ __launch_bounds__(512, 2) void qkv_mma_kernel(
    const float* __restrict__ x,
    const float* __restrict__ wq, const float* __restrict__ bq,
    const float* __restrict__ wk, const float* __restrict__ bk,
    const float* __restrict__ wv, const float* __restrict__ bv,
    const float* __restrict__ pos)
{
    extern __shared__ __align__(16) unsigned short qs[];
    unsigned short* sxh = qs;                    // [256][72]
    unsigned short* sxl = qs + 256 * XSTR;
    unsigned short* swh = qs + 512 * XSTR;       // [64][72] per-m hi
    unsigned short* swl = swh + 64 * XSTR;       // per-m lo
    __shared__ float bsm[192];
    __shared__ float pcs[256];

    const int tid  = threadIdx.x;
    const int b    = blockIdx.y;
    const int pix0 = blockIdx.x * 256;

    if (tid < 256) pcs[tid] = pos[pix0 + tid];
    if (tid < 192) {
        const float* bp = (tid < 64) ? bq : (tid < 128) ? bk : bv;
        bsm[tid] = bp[tid & 63];
    }

    // x transpose + split: thread owns pixel p, 8-channel groups
    {
        const float* xb = x + (size_t)b * CHW + pix0;
        const int p  = tid & 255;
        const int cg = tid >> 8;
        #pragma unroll
        for (int i = 0; i < 4; ++i) {
            int c0 = (cg + 2 * i) * 8;
            unsigned short h[8], l[8];
            #pragma unroll
            for (int j = 0; j < 8; ++j)
                split_bf16(xb[(size_t)(c0 + j) * HW + p], h[j], l[j]);
            uint4 hv, lv;
            hv.x = (uint32_t)h[0] | ((uint32_t)h[1] << 16);
            hv.y = (uint32_t)h[2] | ((uint32_t)h[3] << 16);
            hv.z = (uint32_t)h[4] | ((uint32_t)h[5] << 16);
            hv.w = (uint32_t)h[6] | ((uint32_t)h[7] << 16);
            lv.x = (uint32_t)l[0] | ((uint32_t)l[1] << 16);
            lv.y = (uint32_t)l[2] | ((uint32_t)l[3] << 16);
            lv.z = (uint32_t)l[4] | ((uint32_t)l[5] << 16);
            lv.w = (uint32_t)l[6] | ((uint32_t)l[7] << 16);
            *(uint4*)&sxh[p * XSTR + c0] = hv;
            *(uint4*)&sxl[p * XSTR + c0] = lv;
        }
    }

    const int wid = tid >> 5, lid = tid & 31, g = lid >> 2, t = lid & 3;
    const int m0 = (wid & 3) * 16;      // out-channel tile
    const int n0 = (wid >> 2) * 64;     // pixel tile

    const uint32_t sx_h = sptr(sxh), sx_l = sptr(sxl);
    const uint32_t wb_h = sptr(swh), wb_l = sptr(swl);
    const uint32_t aoff  = (uint32_t)((m0 + (lid & 15)) * XSTR + ((lid & 16) ? 8 : 0)) * 2;
    const uint32_t boff0 = (uint32_t)((n0 + lid) * XSTR) * 2;
    const uint32_t boff1 = (uint32_t)((n0 + 32 + lid) * XSTR) * 2;
    const size_t   ob    = (size_t)b * CHW;

    for (int m = 0; m < 3; ++m) {
        __syncthreads();   // x ready / previous m's ldmatrix reads done
        {
            const float* wp = (m == 0) ? wq : (m == 1) ? wk : wv;
            #pragma unroll
            for (int i = 0; i < 8; ++i) {
                int idx = i * 512 + tid;
                int o = idx >> 6, c = idx & 63;
                unsigned short h, l;
                split_bf16(wp[idx], h, l);
                swh[o * XSTR + c] = h;
                swl[o * XSTR + c] = l;
            }
        }
        __syncthreads();

        float acc[8][4];
        #pragma unroll
        for (int nt = 0; nt < 8; ++nt)
            #pragma unroll
            for (int j = 0; j < 4; ++j) acc[nt][j] = 0.f;

        #pragma unroll
        for (int kk = 0; kk < 4; ++kk) {
            const uint32_t ko = kk * 32;
            uint32_t ah[4], al[4];
            ldm_x4(ah, wb_h + aoff + ko);
            ldm_x4(al, wb_l + aoff + ko);
            #pragma unroll
            for (int hf = 0; hf < 2; ++hf) {
                const uint32_t bo = (hf ? boff1 : boff0) + ko;
                uint32_t bh[8], bl[8];
                ldm_x4(bh,     sx_h + bo);
                ldm_x4(bh + 4, sx_h + bo + 16);
                ldm_x4(bl,     sx_l + bo);
                ldm_x4(bl + 4, sx_l + bo + 16);
                #pragma unroll
                for (int nt = 0; nt < 4; ++nt) {
                    float* ac = acc[hf * 4 + nt];
                    mma_bf16(ac, ah, bh[nt], bh[4 + nt]);
                    mma_bf16(ac, ah, bl[nt], bl[4 + nt]);
                    mma_bf16(ac, al, bh[nt], bh[4 + nt]);
                }
            }
        }

        // epilogue
        const int r0 = m0 + g, r1 = r0 + 8;
        const float b0f = bsm[m * 64 + r0], b1f = bsm[m * 64 + r1];
        #pragma unroll
        for (int nt = 0; nt < 8; ++nt) {
            int px = n0 + nt * 8 + 2 * t;
            float c0 = acc[nt][0] + b0f;
            float c1 = acc[nt][1] + b0f;
            float c2 = acc[nt][2] + b1f;
            float c3 = acc[nt][3] + b1f;
            if (m == 1) {
                float p0 = pcs[px], p1 = pcs[px + 1];
                c0 += p0; c1 += p1; c2 += p0; c3 += p1;
            }
            size_t o0 = ob + (size_t)r0 * HW + pix0 + px;
            size_t o1 = ob + (size_t)r1 * HW + pix0 + px;
            if (m == 2) {
                *(float2*)&g_v[o0] = make_float2(c0, c1);
                *(float2*)&g_v[o1] = make_float2(c2, c3);
            } else {
                unsigned short h0, l0, h1, l1, h2, l2, h3, l3;
                split_bf16(c0, h0, l0);
                split_bf16(c1, h1, l1);
                split_bf16(c2, h2, l2);
                split_bf16(c3, h3, l3);
                uint32_t hp0 = (uint32_t)h0 | ((uint32_t)h1 << 16);
                uint32_t lp0 = (uint32_t)l0 | ((uint32_t)l1 << 16);
                uint32_t hp1 = (uint32_t)h2 | ((uint32_t)h3 << 16);
                uint32_t lp1 = (uint32_t)l2 | ((uint32_t)l3 << 16);
                if (m == 0) {
                    *(uint32_t*)&g_qh[o0] = hp0; *(uint32_t*)&g_ql[o0] = lp0;
                    *(uint32_t*)&g_qh[o1] = hp1; *(uint32_t*)&g_ql[o1] = lp1;
                } else {
                    *(uint32_t*)&g_kh[o0] = hp0; *(uint32_t*)&g_kl[o0] = lp0;
                    *(uint32_t*)&g_kh[o1] = hp1; *(uint32_t*)&g_kl[o1] = lp1;
                }
            }
        }
    }
}

// ---------------------------------------------------------------------------
// Kernel 2: per-(b,c) attention, mma.sync + ldmatrix, bf16x3 split.
// 2 blocks/SM: Q resident (68KB), K processed in two 64-row chunks through a
// reused 34KB buffer. 16 warps, warp tile 32 rows x 16 cols per chunk.
// ---------------------------------------------------------------------------
#define TSTR 136
#define QHALVES (128 * TSTR)     // 17408
#define KHALVES (64 * TSTR)      // 8704
#define AT_SMEM ((2 * QHALVES + 2 * KHALVES) * 2)   // 104448 bytes
#define SSTR 132

__global__ __launch_bounds__(512, 2) void attn_mma_kernel(float* __restrict__ out)
{
    extern __shared__ __align__(16) unsigned short sm[];
    __shared__ float redm[16], reds[16];

    unsigned short* sQh = sm;
    unsigned short* sQl = sm + QHALVES;
    unsigned short* sKh = sm + 2 * QHALVES;
    unsigned short* sKl = sKh + KHALVES;

    const int tid = threadIdx.x, wid = tid >> 5, lid = tid & 31;
    const int g = lid >> 2, t = lid & 3;
    const size_t base = (size_t)blockIdx.x * HW;

    // ---- load Q tiles (hi/lo), coalesced 16B chunks ----
    {
        const uint4* srcH = (const uint4*)(g_qh + base);
        const uint4* srcL = (const uint4*)(g_ql + base);
        #pragma unroll
        for (int i = 0; i < 4; ++i) {
            int cw = i * 512 + tid;
            int row = cw >> 4, c8 = cw & 15;
            *(uint4*)&sQh[row * TSTR + c8 * 8] = srcH[cw];
            *(uint4*)&sQl[row * TSTR + c8 * 8] = srcL[cw];
        }
    }

    const int m0  = (wid & 3) * 32;
    const int n0c = (wid >> 2) * 16;
    const uint32_t qh_b = sptr(sQh), ql_b = sptr(sQl);
    const uint32_t kh_b = sptr(sKh), kl_b = sptr(sKl);
    const uint32_t aoff0 = (uint32_t)((m0 + (lid & 15)) * TSTR + ((lid & 16) ? 8 : 0)) * 2;
    const uint32_t aoff1 = aoff0 + 16 * TSTR * 2;
    const uint32_t boff  = (uint32_t)((n0c + (lid & 15)) * TSTR) * 2 + ((lid & 16) ? 16 : 0);

    float acc[2][2][2][4];   // [chunk][mt][nt][4]
    #pragma unroll
    for (int c = 0; c < 2; ++c)
        #pragma unroll
        for (int mt = 0; mt < 2; ++mt)
            #pragma unroll
            for (int nt = 0; nt < 2; ++nt)
                #pragma unroll
                for (int j = 0; j < 4; ++j) acc[c][mt][nt][j] = 0.f;

    #pragma unroll
    for (int ch = 0; ch < 2; ++ch) {
        // load K chunk (64 rows) into reused buffer
        if (ch) __syncthreads();   // chunk-0 compute done before overwrite
        {
            const uint4* srcH = (const uint4*)(g_kh + base + ch * 64 * FM);
            const uint4* srcL = (const uint4*)(g_kl + base + ch * 64 * FM);
            #pragma unroll
            for (int i = 0; i < 2; ++i) {
                int cw = i * 512 + tid;
                int row = cw >> 4, c8 = cw & 15;
                *(uint4*)&sKh[row * TSTR + c8 * 8] = srcH[cw];
                *(uint4*)&sKl[row * TSTR + c8 * 8] = srcL[cw];
            }
        }
        __syncthreads();

        #pragma unroll
        for (int kk = 0; kk < 8; ++kk) {
            const uint32_t ko = kk * 32;
            uint32_t ah[2][4], al[2][4], bh[4], bl[4];
            ldm_x4(ah[0], qh_b + aoff0 + ko);
            ldm_x4(ah[1], qh_b + aoff1 + ko);
            ldm_x4(al[0], ql_b + aoff0 + ko);
            ldm_x4(al[1], ql_b + aoff1 + ko);
            ldm_x4(bh, kh_b + boff + ko);
            ldm_x4(bl, kl_b + boff + ko);
            #pragma unroll
            for (int mt = 0; mt < 2; ++mt)
                #pragma unroll
                for (int nt = 0; nt < 2; ++nt) {
                    float* ac = acc[ch][mt][nt];
                    mma_bf16(ac, ah[mt], bh[nt], bh[2 + nt]);
                    mma_bf16(ac, ah[mt], bl[nt], bl[2 + nt]);
                    mma_bf16(ac, al[mt], bh[nt], bh[2 + nt]);
                }
        }
    }

    float* l = &acc[0][0][0][0];   // 32 logits per lane

    // ---- global max ----
    float mx = l[0];
    #pragma unroll
    for (int j = 1; j < 32; ++j) mx = fmaxf(mx, l[j]);
    #pragma unroll
    for (int o = 16; o; o >>= 1) mx = fmaxf(mx, __shfl_xor_sync(0xffffffffu, mx, o));
    if (lid == 0) redm[wid] = mx;
    __syncthreads();
    float gm = redm[0];
    #pragma unroll
    for (int w = 1; w < 16; ++w) gm = fmaxf(gm, redm[w]);

    // ---- exp + global sum ----
    float s = 0.f;
    #pragma unroll
    for (int j = 0; j < 32; ++j) {
        l[j] = __expf(l[j] - gm);
        s += l[j];
    }
    #pragma unroll
    for (int o = 16; o; o >>= 1) s += __shfl_xor_sync(0xffffffffu, s, o);
    if (lid == 0) reds[wid] = s;
    __syncthreads();
    float gs = 0.f;
    #pragma unroll
    for (int w = 0; w < 16; ++w) gs += reds[w];
    const float inv = 1.0f / gs;

    // ---- stage normalized att into smem (tiles no longer needed) ----
    float* stg = (float*)sm;
    #pragma unroll
    for (int ch = 0; ch < 2; ++ch)
        #pragma unroll
        for (int mt = 0; mt < 2; ++mt) {
            const int r0 = m0 + mt * 16 + g;
            #pragma unroll
            for (int nt = 0; nt < 2; ++nt) {
                const int cN = ch * 64 + n0c + nt * 8 + 2 * t;
                stg[r0 * SSTR + cN]           = acc[ch][mt][nt][0] * inv;
                stg[r0 * SSTR + cN + 1]       = acc[ch][mt][nt][1] * inv;
                stg[(r0 + 8) * SSTR + cN]     = acc[ch][mt][nt][2] * inv;
                stg[(r0 + 8) * SSTR + cN + 1] = acc[ch][mt][nt][3] * inv;
            }
        }
    __syncthreads();

    // ---- coalesced out = att * v ----
    const float* vg = g_v + base;
    float* og = out + base;
    #pragma unroll
    for (int i = 0; i < 32; ++i) {
        int idx = i * 512 + tid;
        int r = idx >> 7, c = idx & 127;
        og[idx] = stg[r * SSTR + c] * vg[idx];
    }
}

// ---------------------------------------------------------------------------
extern "C" void kernel_launch(void* const* d_in, const int* in_sizes, int n_in,
                              void* d_out, int out_size)
{
    (void)in_sizes; (void)n_in; (void)out_size;
    const float* x  = (const float*)d_in[0];
    const float* wq = (const float*)d_in[1];
    const float* bq = (const float*)d_in[2];
    const float* wk = (const float*)d_in[3];
    const float* bk = (const float*)d_in[4];
    const float* wv = (const float*)d_in[5];
    const float* bv = (const float*)d_in[6];
    const float* pc = (const float*)d_in[7];
    float* out = (float*)d_out;

    cudaFuncSetAttribute(qkv_mma_kernel, cudaFuncAttributeMaxDynamicSharedMemorySize, QKV_SMEM);
    cudaFuncSetAttribute(attn_mma_kernel, cudaFuncAttributeMaxDynamicSharedMemorySize, AT_SMEM);

    qkv_mma_kernel<<<dim3(HW / 256, BATCH), 512, QKV_SMEM>>>(x, wq, bq, wk, bk, wv, bv, pc);
    attn_mma_kernel<<<BATCH * CH, 512, AT_SMEM>>>(out);
}